// round 13
// baseline (speedup 1.0000x reference)
#include <cuda_runtime.h>
#include <math.h>

#define NBBINS 50
#define TI 64         // i-points per pcf block (= blockDim.x); 576 blocks -> good balance
#define TILE_J 64     // j-points per block / per bbox tile
#define SORT_N 2048   // padded point count (na=nb=1536)
#define CHUNKS 64     // SORT_N / 32
#define NKEYS 257     // 256 morton cells + pad sentinel
#define MAXTILES (SORT_N / TILE_J)
#define MAX_WARPS 4096
#define WB 64         // weight-kernel block size: 24 blocks -> 24 SMs active
#define FAR_POISON 6.0e4f   // finite poison: d2~3.6e9, q~-1e14 -> ex2=0, NO inf/NaN

// Scratch (device allocation forbidden).
__device__ float g_Ax[SORT_N];
__device__ float g_Ay[SORT_N];
__device__ int   g_Aorig[SORT_N];
__device__ float g_Bx[SORT_N];
__device__ float g_By[SORT_N];
__device__ int   g_Borig[SORT_N];
__device__ float g_Btile[MAXTILES * 4];        // minx, maxx, miny, maxy per j-tile
__device__ float g_wT[NBBINS * SORT_N];        // [b][i] -> coalesced epilogue
__device__ float g_part[MAX_WARPS * NBBINS];   // [warp][b] partials

__device__ __forceinline__ double rmax_d() {
    // RMAX = 2*sqrt(1/(2*sqrt(3)*NPOINTS)), NPOINTS = 1536 in the reference.
    return 2.0 * sqrt(1.0 / (2.0 * sqrt(3.0) * 1536.0));
}

__device__ __forceinline__ unsigned spread4(unsigned v) {
    v = (v | (v << 2)) & 0x33u;
    v = (v | (v << 1)) & 0x55u;
    return v;
}

// Single MUFU.EX2 regardless of compile flags; ex2(very negative) -> exact 0.
__device__ __forceinline__ float ex2(float x) {
    float r;
    asm("ex2.approx.ftz.f32 %0, %1;" : "=f"(r) : "f"(x));
    return r;
}
// Single MUFU.SQRT; sqrt.approx(0) = 0 (no rsqrt NaN path).
__device__ __forceinline__ float sqrt_approx(float x) {
    float r;
    asm("sqrt.approx.ftz.f32 %0, %1;" : "=f"(r) : "f"(x));
    return r;
}

// ---------------------------------------------------------------------------
// Kernel 0: deterministic stable counting sort (16x16 Morton) of A AND B,
// plus per-j-tile bounding boxes for B. One block, 1024 threads.
// Stable rank = rowoff[key] + sum_{chunk'<chunk} cnt[key][chunk'] + intra-
// chunk ballot rank -> bitwise deterministic, order = (key, orig idx).
// ---------------------------------------------------------------------------
struct SortSmem {
    unsigned char cnt[NKEYS * CHUNKS];
    int rowsum[NKEYS];
    int rowoff[NKEYS];
};

__device__ void counting_sort(SortSmem* sm, const float* __restrict__ src, int n,
                              float* ox, float* oy, int* oorig) {
    const int t = threadIdx.x;
    const int lane = t & 31;

    for (int k = t; k < NKEYS * CHUNKS; k += 1024) sm->cnt[k] = 0;
    __syncthreads();

    int mykey[2];
#pragma unroll
    for (int p = 0; p < 2; ++p) {
        int idx = t + p * 1024;
        int key = 256;                               // pad sentinel, sorts last
        if (idx < n) {
            float x = src[idx * 3 + 0];
            float y = src[idx * 3 + 1];
            int cx = min(15, max(0, (int)(x * 16.0f)));
            int cy = min(15, max(0, (int)(y * 16.0f)));
            key = (int)((spread4((unsigned)cy) << 1) | spread4((unsigned)cx));
        }
        mykey[p] = key;
        unsigned mask = __match_any_sync(0xffffffffu, key);
        if (lane == __ffs(mask) - 1)
            sm->cnt[key * CHUNKS + (idx >> 5)] = (unsigned char)__popc(mask);
    }
    __syncthreads();

    if (t < NKEYS) {
        int s = 0;
        for (int c = 0; c < CHUNKS; ++c) s += sm->cnt[t * CHUNKS + c];
        sm->rowsum[t] = s;
    }
    __syncthreads();
    if (t == 0) {
        int run = 0;
        for (int k = 0; k < NKEYS; ++k) { sm->rowoff[k] = run; run += sm->rowsum[k]; }
    }
    __syncthreads();

#pragma unroll
    for (int p = 0; p < 2; ++p) {
        int idx = t + p * 1024;
        int key = mykey[p];
        unsigned mask = __match_any_sync(0xffffffffu, key);
        int intrarank = __popc(mask & ((1u << lane) - 1u));
        int cp = 0;
        for (int c = 0; c < (idx >> 5); ++c) cp += sm->cnt[key * CHUNKS + c];
        int pos = sm->rowoff[key] + cp + intrarank;
        if (idx < n) {
            ox[pos] = src[idx * 3 + 0];
            oy[pos] = src[idx * 3 + 1];
            oorig[pos] = idx;
        } else {
            ox[pos] = FAR_POISON;   // finite far poison: contributes exact 0
            oy[pos] = FAR_POISON;
            oorig[pos] = -1;
        }
    }
    __syncthreads();
}

__global__ void __launch_bounds__(1024) sort_kernel(
    const float* __restrict__ A, const float* __restrict__ B, int na, int nb)
{
    __shared__ SortSmem sm;
    counting_sort(&sm, A, na, g_Ax, g_Ay, g_Aorig);
    counting_sort(&sm, B, nb, g_Bx, g_By, g_Borig);

    // Per-j-tile bounding boxes over sorted B (real points only).
    int t = threadIdx.x;
    int ntiles = (nb + TILE_J - 1) / TILE_J;
    if (t < ntiles) {
        int j0 = t * TILE_J;
        int cnt = min(TILE_J, nb - j0);
        float mnx = 1e30f, mxx = -1e30f, mny = 1e30f, mxy = -1e30f;
        for (int k = 0; k < cnt; ++k) {
            float x = g_Bx[j0 + k], y = g_By[j0 + k];
            mnx = fminf(mnx, x); mxx = fmaxf(mxx, x);
            mny = fminf(mny, y); mxy = fmaxf(mxy, y);
        }
        g_Btile[t * 4 + 0] = mnx;
        g_Btile[t * 4 + 1] = mxx;
        g_Btile[t * 4 + 2] = mny;
        g_Btile[t * 4 + 3] = mxy;
    }
}

// ---------------------------------------------------------------------------
// Kernel 1: perimeter weights, thread-per-point; atan2 once per triggered
// side; interior points do no trig. 64-thread blocks -> 24 blocks spread the
// boundary-heavy warps across 24 SMs. Transposed store g_wT[b][i].
// Bin loops force-unrolled so full[] stays in registers (no LDL/STL spill).
// ---------------------------------------------------------------------------
__global__ void __launch_bounds__(WB) weight_kernel(int na) {
    int i = blockIdx.x * WB + threadIdx.x;
    if (i >= na) return;

    const float rmax = (float)rmax_d();
    const float TWO_PI = 6.283185307179586f;
    const float r_last = 5.0f * rmax;               // RS[49]

    float x = g_Ax[i], y = g_Ay[i];

    float full[NBBINS];
#pragma unroll
    for (int b = 0; b < NBBINS; ++b) full[b] = TWO_PI;

    float sdx[4] = { x, 1.0f - x, y, 1.0f - y };
    float sdy[4] = { y, y,         x, x        };
#pragma unroll
    for (int s = 0; s < 4; ++s) {
        float dx = sdx[s], dy = sdy[s];
        if (dx < r_last) {
            float a1 = atan2f(dy, dx);
            float a2 = atan2f(1.0f - dy, dx);
#pragma unroll
            for (int b = 0; b < NBBINS; ++b) {
                float r = 0.1f * (float)(b + 1) * rmax;
                if (r > dx) {                        // reference: RS > dx strict
                    float ratio = fminf(dx / r, 1.0f);    // dx >= 0 always
                    float alpha = acosf(ratio);
                    full[b] -= fminf(alpha, a1) + fminf(alpha, a2);
                }
            }
        }
    }
#pragma unroll
    for (int b = 0; b < NBBINS; ++b) {
        float per = fminf(fmaxf(full[b] / TWO_PI, 0.0f), 1.0f);
        float w = fminf(1.0f / fmaxf(per, 1e-9f), 4.0f);   // clip(w,0,4)
        g_wT[b * SORT_N + i] = w;
    }
}

// ---------------------------------------------------------------------------
// Kernel 2: main accumulation, (sorted i) x (sorted j tile).
// val_b = exp(-(0.4(b+1)-s4)^2) = ex2( K2[b]*s4 + K1[b] - L*s4^2 ),
//   K1[b] = -L*0.16*(b+1)^2, K2[b] = L*0.8*(b+1), L = log2(e), s4 = 4d/RMAX.
// Two-level pruning: warp-vs-tile-bbox skip, then per-j warp vote.
// All poison paths FINITE: diagonal s4=3e18 -> P~1.3e37 -> q~-1.3e37 -> 0;
// pad/invalid coords 6e4 -> q~-1e14 -> 0. No inf-inf NaN possible.
// ---------------------------------------------------------------------------
__global__ void __launch_bounds__(TI) pcf_kernel(
    const int* __restrict__ same_cat, int na, int nb)
{
    __shared__ float sjx[TILE_J];
    __shared__ float sjy[TILE_J];
    __shared__ int   sjo[TILE_J];

    const int i = blockIdx.x * TI + threadIdx.x;
    const bool valid = (i < na);
    const int same = same_cat[0];

    const float L = 1.4426950408889634f;
    const float rmax = (float)rmax_d();
    const float s_scale = 4.0f / rmax;                   // d -> 4*d/RMAX
    const float thresh2 = (26.0f / s_scale) * (26.0f / s_scale);

    const float xi = valid ? g_Ax[i] : FAR_POISON;
    const float yi = valid ? g_Ay[i] : FAR_POISON;
    const int   oi = valid ? g_Aorig[i] : -1;

    float acc[NBBINS];
#pragma unroll
    for (int b = 0; b < NBBINS; ++b) acc[b] = 0.0f;

    const int tile = blockIdx.y;
    const int j0 = tile * TILE_J;
    const int cnt = min(TILE_J, nb - j0);

    if (threadIdx.x < cnt) {
        int j = j0 + threadIdx.x;
        sjx[threadIdx.x] = g_Bx[j];
        sjy[threadIdx.x] = g_By[j];
        sjo[threadIdx.x] = g_Borig[j];
    }
    __syncthreads();

    // Warp-vs-tile bbox prune (conservative: dist to box <= any point dist).
    float bmnx = g_Btile[tile * 4 + 0];
    float bmxx = g_Btile[tile * 4 + 1];
    float bmny = g_Btile[tile * 4 + 2];
    float bmxy = g_Btile[tile * 4 + 3];
    float ddx = fmaxf(fmaxf(bmnx - xi, xi - bmxx), 0.0f);
    float ddy = fmaxf(fmaxf(bmny - yi, yi - bmxy), 0.0f);
    bool tile_near = !__all_sync(0xffffffffu, ddx * ddx + ddy * ddy > thresh2);

    if (tile_near) {
        for (int k = 0; k < cnt; ++k) {
            float dx = xi - sjx[k];
            float dy = yi - sjy[k];
            float d2 = dx * dx + dy * dy;

            if (__all_sync(0xffffffffu, d2 > thresh2)) continue;

            float s4 = sqrt_approx(d2) * s_scale;
            if (same && oi == sjo[k]) s4 = 3.0e18f;      // diagonal -> exact 0

            float P = L * s4 * s4;                       // finite on all paths
#pragma unroll
            for (int b = 0; b < NBBINS; ++b) {
                const float K1 = -L * 0.16f * (float)((b + 1) * (b + 1));
                const float K2 =  L * 0.80f * (float)(b + 1);
                acc[b] += ex2(fmaf(K2, s4, K1) - P);
            }
        }
    }

    // Weighted warp-reduction; lane 0 writes 50 partials (deterministic).
    const int wslot = (blockIdx.y * gridDim.x + blockIdx.x) * (TI / 32)
                    + (threadIdx.x >> 5);
    float* part = g_part + (size_t)wslot * NBBINS;
    const int iw = valid ? i : 0;
#pragma unroll
    for (int b = 0; b < NBBINS; ++b) {
        float wv = valid ? g_wT[b * SORT_N + iw] : 0.0f;   // coalesced
        float v = acc[b] * wv;
        v += __shfl_down_sync(0xffffffffu, v, 16);
        v += __shfl_down_sync(0xffffffffu, v, 8);
        v += __shfl_down_sync(0xffffffffu, v, 4);
        v += __shfl_down_sync(0xffffffffu, v, 2);
        v += __shfl_down_sync(0xffffffffu, v, 1);
        if ((threadIdx.x & 31) == 0) part[b] = v;
    }
}

// ---------------------------------------------------------------------------
// Kernel 3: deterministic reduction of per-warp partials + normalization.
// One block per bin; fixed strided serial order + fixed shared tree.
// ---------------------------------------------------------------------------
__global__ void __launch_bounds__(256) finalize_kernel(
    float* __restrict__ out, int na, int nb, int nwarps)
{
    __shared__ float red[256];
    const int b = blockIdx.x;
    const int t = threadIdx.x;

    float sum = 0.0f;
    for (int w = t; w < nwarps; w += 256)
        sum += g_part[(size_t)w * NBBINS + b];
    red[t] = sum;
    __syncthreads();
#pragma unroll
    for (int s = 128; s > 0; s >>= 1) {
        if (t < s) red[t] += red[t + s];
        __syncthreads();
    }

    if (t == 0) {
        double rmax = rmax_d();
        double rs = (double)(b + 1) * 0.1 * rmax;
        double inner = fmax(0.0, rs - 0.5 * rmax);
        double outer = rs + 0.5 * rmax;
        const double PI = 3.14159265358979323846;
        double area = PI * (outer * outer - inner * inner);
        double gf = 1.0 / (sqrt(PI) * 0.25);   // 1/(sqrt(pi)*SIGMA)

        double pcf1 = gf * (double)red[0] / (double)na / (area * (double)nb);
        out[2 * b + 0] = (float)(rs / rmax);
        out[2 * b + 1] = (float)pcf1;
    }
}

// ---------------------------------------------------------------------------
extern "C" void kernel_launch(void* const* d_in, const int* in_sizes, int n_in,
                              void* d_out, int out_size) {
    const float* A = (const float*)d_in[0];        // disks_a [na,3]
    const float* B = (const float*)d_in[1];        // disks_b [nb,3]
    const int* same = (const int*)d_in[2];         // same_category scalar
    float* out = (float*)d_out;                    // [NBBINS, 2]

    int na = in_sizes[0] / 3;
    int nb = in_sizes[1] / 3;

    sort_kernel<<<1, 1024>>>(A, B, na, nb);

    int wblocks = (na + WB - 1) / WB;
    weight_kernel<<<wblocks, WB>>>(na);

    dim3 grid((na + TI - 1) / TI, (nb + TILE_J - 1) / TILE_J);
    pcf_kernel<<<grid, TI>>>(same, na, nb);

    int nwarps = grid.x * grid.y * (TI / 32);
    finalize_kernel<<<NBBINS, 256>>>(out, na, nb, nwarps);
}